// round 16
// baseline (speedup 1.0000x reference)
#include <cuda_runtime.h>

// Temporal cosine regularizer, single fused kernel (R16 = R11 + full-wave grid).
//   out = -0.02/(N-1) * sum_i <x_i,x_{i+1}> / (max(||x_i||,eps)*max(||x_{i+1}||,eps))
//
// HBM-bound, 512 MiB read-once. Champion lineage: 256 thr / 8 elems/thread
// register pipeline (R2) + __ldcg (R8) + serpentine row order (R11) + fused
// deterministic finalize. R16 changes ONE constant: RPB 64 -> 56, so the grid
// is 1171 blocks ~= 7.91 blocks/SM (vs 6.92 at 1024), filling the 8-block/SM
// single-wave capacity: +14% resident warps, and BW here tracks warp count.
// Extra boundary overlap (1.56% -> 1.79%) is L2-only under serpentine order
// (second touch of each shared row is an L2 hit), so DRAM bytes are unchanged.

#define COLS     2048
#define RPB      56
#define NTHREADS 256

__device__ float        g_partials[8192];
__device__ unsigned int g_count = 0;

__device__ __forceinline__ float warp_reduce_f(float v) {
#pragma unroll
    for (int o = 16; o > 0; o >>= 1) v += __shfl_xor_sync(0xffffffffu, v, o);
    return v;
}

__global__ void __launch_bounds__(NTHREADS)
pair_dot_fused_kernel(const float* __restrict__ x, int N, float* __restrict__ out) {
    __shared__ float s_sq[RPB + 1][8];
    __shared__ float s_dp[RPB][8];
    __shared__ bool  s_last;

    const int tid  = threadIdx.x;
    const int lane = tid & 31;
    const int warp = tid >> 5;
    const int r0   = blockIdx.x * RPB;
    const bool fwd = (blockIdx.x & 1) == 0;   // serpentine direction

    // First streamed local row index: 0 (fwd) or RPB (bwd).
    float prev[8];
    {
        const int i0 = fwd ? 0 : RPB;
        const int r  = r0 + i0;
        float sq = 0.0f;
        if (r < N) {
            const float4* rp = reinterpret_cast<const float4*>(x + (size_t)r * COLS);
            float4 a = __ldcg(rp + tid);
            float4 b = __ldcg(rp + tid + NTHREADS);
            prev[0]=a.x; prev[1]=a.y; prev[2]=a.z; prev[3]=a.w;
            prev[4]=b.x; prev[5]=b.y; prev[6]=b.z; prev[7]=b.w;
#pragma unroll
            for (int j = 0; j < 8; ++j) sq = fmaf(prev[j], prev[j], sq);
        } else {
#pragma unroll
            for (int j = 0; j < 8; ++j) prev[j] = 0.0f;
        }
        sq = warp_reduce_f(sq);
        if (lane == 0) s_sq[i0][warp] = sq;
    }

    // Remaining RPB rows. fwd: i = k (rows 1..RPB), dot slot i-1.
    //                     bwd: i = RPB-k (rows RPB-1..0), dot slot i.
#pragma unroll 4
    for (int k = 1; k <= RPB; ++k) {
        const int i = fwd ? k : (RPB - k);
        const int r = r0 + i;
        float sq = 0.0f, dp = 0.0f;
        if (r < N) {
            const float4* rp = reinterpret_cast<const float4*>(x + (size_t)r * COLS);
            float4 a = __ldcg(rp + tid);
            float4 b = __ldcg(rp + tid + NTHREADS);
            float cur[8] = {a.x, a.y, a.z, a.w, b.x, b.y, b.z, b.w};
#pragma unroll
            for (int j = 0; j < 8; ++j) {
                sq = fmaf(cur[j], cur[j], sq);
                dp = fmaf(cur[j], prev[j], dp);
                prev[j] = cur[j];
            }
        }
        sq = warp_reduce_f(sq);
        dp = warp_reduce_f(dp);
        if (lane == 0) {
            s_sq[i][warp] = sq;
            s_dp[fwd ? (i - 1) : i][warp] = dp;  // dot(r0+slot, r0+slot+1)
        }
    }
    __syncthreads();

    // Warp 0: cosine terms for dot slots j = 0..RPB-1 (dot index r0+j),
    // valid when r0+j+1 < N. fp64 accumulate, fixed order.
    if (warp == 0) {
        double acc = 0.0;
        for (int j = lane; j < RPB; j += 32) {
            if (r0 + j + 1 < N) {
                float n2a = 0.0f, n2b = 0.0f, d8 = 0.0f;
#pragma unroll
                for (int w = 0; w < 8; ++w) {
                    n2a += s_sq[j][w];
                    n2b += s_sq[j + 1][w];
                    d8  += s_dp[j][w];
                }
                float na = fmaxf(sqrtf(n2a), 1e-12f);
                float nb = fmaxf(sqrtf(n2b), 1e-12f);
                acc += (double)(d8 / (na * nb));
            }
        }
#pragma unroll
        for (int o = 16; o > 0; o >>= 1)
            acc += __shfl_xor_sync(0xffffffffu, acc, o);
        if (lane == 0) g_partials[blockIdx.x] = (float)acc;
    }

    // ---- last-block-done: deterministic final reduction ----
    __threadfence();
    if (tid == 0) {
        unsigned int prev_cnt = atomicAdd(&g_count, 1u);
        s_last = (prev_cnt == gridDim.x - 1);
    }
    __syncthreads();

    if (s_last) {
        __shared__ double sd[NTHREADS];
        const int nb = gridDim.x;
        double a = 0.0;
        for (int i = tid; i < nb; i += NTHREADS)
            a += (double)__ldcg(&g_partials[i]);
        sd[tid] = a;
        __syncthreads();
#pragma unroll
        for (int o = NTHREADS / 2; o > 0; o >>= 1) {
            if (tid < o) sd[tid] += sd[tid + o];
            __syncthreads();
        }
        if (tid == 0) {
            out[0] = (float)(-2.0 * 0.01 * sd[0] / (double)(N - 1));
            g_count = 0;  // reset for next graph replay
        }
    }
}

extern "C" void kernel_launch(void* const* d_in, const int* in_sizes, int n_in,
                              void* d_out, int out_size) {
    const float* x = (const float*)d_in[0];
    const int N = in_sizes[0] / COLS;            // 65536
    const int nblocks = (N - 1 + RPB - 1) / RPB; // 1171
    pair_dot_fused_kernel<<<nblocks, NTHREADS>>>(x, N, (float*)d_out);
}

// round 17
// speedup vs baseline: 1.0468x; 1.0468x over previous
#include <cuda_runtime.h>

// Temporal cosine regularizer, single fused kernel (R17 = R11 + __ldcs).
//   out = -0.02/(N-1) * sum_i <x_i,x_{i+1}> / (max(||x_i||,eps)*max(||x_{i+1}||,eps))
//
// HBM-bound, 512 MiB read-once, 540 MB measured (99.5% byte efficiency).
// Champion operating point (all axes ablated on-silicon):
//  - 256 thr, 8 elems/thread, RPB=64 register pipeline, no per-row syncs
//  - serpentine row order (boundary rows = L2 hits)
//  - ~55 warps/SM: measured BW peak (84% occ beat both 61% and 94%)
//  - fused deterministic last-block finalize
// R17 tests the last cache-policy cell: __ldcs (evict-first streaming) vs
// __ldcg. The 512 MB stream cycles L2 ~4x; evict-first cuts way-allocation
// churn. Boundary reuse survives: under serpentine the second touch is
// temporally adjacent. Same instruction shape -> zero register risk.

#define COLS     2048
#define RPB      64
#define NTHREADS 256

__device__ float        g_partials[8192];
__device__ unsigned int g_count = 0;

__device__ __forceinline__ float warp_reduce_f(float v) {
#pragma unroll
    for (int o = 16; o > 0; o >>= 1) v += __shfl_xor_sync(0xffffffffu, v, o);
    return v;
}

__global__ void __launch_bounds__(NTHREADS)
pair_dot_fused_kernel(const float* __restrict__ x, int N, float* __restrict__ out) {
    __shared__ float s_sq[RPB + 1][8];
    __shared__ float s_dp[RPB][8];
    __shared__ bool  s_last;

    const int tid  = threadIdx.x;
    const int lane = tid & 31;
    const int warp = tid >> 5;
    const int r0   = blockIdx.x * RPB;
    const bool fwd = (blockIdx.x & 1) == 0;   // serpentine direction

    // First streamed local row index: 0 (fwd) or RPB (bwd).
    float prev[8];
    {
        const int i0 = fwd ? 0 : RPB;
        const int r  = r0 + i0;
        float sq = 0.0f;
        if (r < N) {
            const float4* rp = reinterpret_cast<const float4*>(x + (size_t)r * COLS);
            float4 a = __ldcs(rp + tid);
            float4 b = __ldcs(rp + tid + NTHREADS);
            prev[0]=a.x; prev[1]=a.y; prev[2]=a.z; prev[3]=a.w;
            prev[4]=b.x; prev[5]=b.y; prev[6]=b.z; prev[7]=b.w;
#pragma unroll
            for (int j = 0; j < 8; ++j) sq = fmaf(prev[j], prev[j], sq);
        } else {
#pragma unroll
            for (int j = 0; j < 8; ++j) prev[j] = 0.0f;
        }
        sq = warp_reduce_f(sq);
        if (lane == 0) s_sq[i0][warp] = sq;
    }

    // Remaining RPB rows. fwd: i = k (rows 1..RPB), dot slot i-1.
    //                     bwd: i = RPB-k (rows RPB-1..0), dot slot i.
#pragma unroll 4
    for (int k = 1; k <= RPB; ++k) {
        const int i = fwd ? k : (RPB - k);
        const int r = r0 + i;
        float sq = 0.0f, dp = 0.0f;
        if (r < N) {
            const float4* rp = reinterpret_cast<const float4*>(x + (size_t)r * COLS);
            float4 a = __ldcs(rp + tid);
            float4 b = __ldcs(rp + tid + NTHREADS);
            float cur[8] = {a.x, a.y, a.z, a.w, b.x, b.y, b.z, b.w};
#pragma unroll
            for (int j = 0; j < 8; ++j) {
                sq = fmaf(cur[j], cur[j], sq);
                dp = fmaf(cur[j], prev[j], dp);
                prev[j] = cur[j];
            }
        }
        sq = warp_reduce_f(sq);
        dp = warp_reduce_f(dp);
        if (lane == 0) {
            s_sq[i][warp] = sq;
            s_dp[fwd ? (i - 1) : i][warp] = dp;  // dot(r0+slot, r0+slot+1)
        }
    }
    __syncthreads();

    // Warp 0: cosine terms for dot slots j = 0..RPB-1 (dot index r0+j),
    // valid when r0+j+1 < N. fp64 accumulate, fixed order.
    if (warp == 0) {
        double acc = 0.0;
        for (int j = lane; j < RPB; j += 32) {
            if (r0 + j + 1 < N) {
                float n2a = 0.0f, n2b = 0.0f, d8 = 0.0f;
#pragma unroll
                for (int w = 0; w < 8; ++w) {
                    n2a += s_sq[j][w];
                    n2b += s_sq[j + 1][w];
                    d8  += s_dp[j][w];
                }
                float na = fmaxf(sqrtf(n2a), 1e-12f);
                float nb = fmaxf(sqrtf(n2b), 1e-12f);
                acc += (double)(d8 / (na * nb));
            }
        }
#pragma unroll
        for (int o = 16; o > 0; o >>= 1)
            acc += __shfl_xor_sync(0xffffffffu, acc, o);
        if (lane == 0) g_partials[blockIdx.x] = (float)acc;
    }

    // ---- last-block-done: deterministic final reduction ----
    __threadfence();
    if (tid == 0) {
        unsigned int prev_cnt = atomicAdd(&g_count, 1u);
        s_last = (prev_cnt == gridDim.x - 1);
    }
    __syncthreads();

    if (s_last) {
        __shared__ double sd[NTHREADS];
        const int nb = gridDim.x;
        double a = 0.0;
        for (int i = tid; i < nb; i += NTHREADS)
            a += (double)__ldcg(&g_partials[i]);
        sd[tid] = a;
        __syncthreads();
#pragma unroll
        for (int o = NTHREADS / 2; o > 0; o >>= 1) {
            if (tid < o) sd[tid] += sd[tid + o];
            __syncthreads();
        }
        if (tid == 0) {
            out[0] = (float)(-2.0 * 0.01 * sd[0] / (double)(N - 1));
            g_count = 0;  // reset for next graph replay
        }
    }
}

extern "C" void kernel_launch(void* const* d_in, const int* in_sizes, int n_in,
                              void* d_out, int out_size) {
    const float* x = (const float*)d_in[0];
    const int N = in_sizes[0] / COLS;            // 65536
    const int nblocks = (N - 1 + RPB - 1) / RPB; // 1024
    pair_dot_fused_kernel<<<nblocks, NTHREADS>>>(x, N, (float*)d_out);
}